// round 10
// baseline (speedup 1.0000x reference)
#include <cuda_runtime.h>
#include <cuda_fp16.h>
#include <math.h>

// ---------------------------------------------------------------------------
// Problem constants
// ---------------------------------------------------------------------------
#define B       16384
#define HID     512
#define NDETER  512
#define NGATE   1536
#define KIN     1084
#define KOBS    5632
#define NSTATS  1024
#define OUTW    2560
#define LNEPS   1e-3f
#define UNIMIX  0.01f
#define LO_SCALE    2048.0f
#define LO_UNSCALE  (1.0f / 2048.0f)

// ---------------------------------------------------------------------------
// Scratch (device globals; no runtime allocation allowed)
// ---------------------------------------------------------------------------
__device__ float g_xbuf[(size_t)B * HID];
__device__ float g_gi  [(size_t)B * NGATE];
__device__ float g_gh  [(size_t)B * NGATE];
__device__ float g_ybuf[(size_t)B * HID];

// ---------------------------------------------------------------------------
// Helpers
// ---------------------------------------------------------------------------
__device__ __forceinline__ unsigned smem_u32(const void* p) {
    unsigned a;
    asm("{ .reg .u64 t; cvta.to.shared.u64 t, %1; cvt.u32.u64 %0, t; }"
        : "=r"(a) : "l"(p));
    return a;
}

#define MMA16816(acc, a, b0v, b1v)                                            \
    asm volatile(                                                             \
        "mma.sync.aligned.m16n8k16.row.col.f32.f16.f16.f32 "                  \
        "{%0,%1,%2,%3}, {%4,%5,%6,%7}, {%8,%9}, {%0,%1,%2,%3};"               \
        : "+f"((acc)[0]), "+f"((acc)[1]), "+f"((acc)[2]), "+f"((acc)[3])      \
        : "r"((a)[0]), "r"((a)[1]), "r"((a)[2]), "r"((a)[3]),                 \
          "r"(b0v), "r"(b1v))

#define LDMX4(r0, r1, r2, r3, addr)                                           \
    asm volatile("ldmatrix.sync.aligned.m8n8.x4.shared.b16 {%0,%1,%2,%3}, [%4];" \
        : "=r"(r0), "=r"(r1), "=r"(r2), "=r"(r3) : "r"(addr))

#define BAR_SYNC(id)   asm volatile("bar.sync %0, 384;"   :: "r"(id) : "memory")
#define BAR_ARRIVE(id) asm volatile("bar.arrive %0, 384;" :: "r"(id) : "memory")

// ---------------------------------------------------------------------------
// Warp-specialized fp16-split (Ootomo) HMMA GEMM:
//   C[M,N] = A[M,K] * W[N,K]^T (+ bias)
// x = hi + lo/2048 (fp16).  acc0 += hi*hi;  acc1 += hi*lo + lo*hi;
// C = acc0 + acc1/2048.  fp32 accumulators.
// CTA tile 128(M) x 64(N), K-chunk 32. 384 threads:
//   warps 0-7  = consumers (4Mx2N, warp tile 32x32): LDSM + MMA only
//   warps 8-11 = producers: LDG + hi/lo convert + STS only
// 3-stage smem ring (32KB stride), named-barrier handshake:
//   full[s] = id 1+s (producers arrive, consumers sync)
//   empty[s]= id 4+s (consumers arrive, producers sync; skipped first 3)
// Stage layout: AH@0 (10240B), AL@10240, BH@20480 (5120B), BL@25600. Pitch 80B.
// Fragment values + per-output k-accumulation order identical to rounds 8/9
// -> bit-identical results (rel_err must stay 9.778108e-4).
// ---------------------------------------------------------------------------
#define BKF     32
#define PITCH   80
#define ALO     10240u
#define BH_REL  20480u
#define BLO     5120u
#define STG     32768u
#define NSTAGE  3
#define GEMM_SMEM (3 * 32768)

__global__ __launch_bounds__(384, 1)
void gemm_hmma(const float* __restrict__ A1, int lda1, int K1,
               const float* __restrict__ A2, int lda2,
               const float* __restrict__ W, const float* __restrict__ bias,
               float* __restrict__ C, int ldc, int K)
{
    extern __shared__ char smem[];
    const unsigned sb = smem_u32(smem);
    const int tid  = threadIdx.x;
    const int lane = tid & 31;
    const int wid  = tid >> 5;              // 0..11
    const int mBase = blockIdx.y * 128;
    const int nBase = blockIdx.x * 64;
    const int nch = (K + BKF - 1) / BKF;

    if (wid >= 8) {
        // =================== PRODUCER (warps 8-11, 128 threads) ============
        const int pt = tid - 256;           // 0..127
        const float* A2b = A2 ? A2 : A1;
        const int    ld2 = A2 ? lda2 : 0;

        int s = 0;
        for (int it = 0; it < nch; ++it) {
            const int k0 = it * BKF;
            const bool seg1 = (k0 < K1);
            const int  kA   = seg1 ? k0 : k0 - K1;
            const int  rem  = K - k0;

            // ---- LDG 12 float4 (A: 128 rows, W: 64 rows; 8 f4-cols) ----
            float4 v[12];
#pragma unroll
            for (int q = 0; q < 12; ++q) {
                const int idx = pt + q * 128;       // 0..1535
                const int row = idx >> 3;           // 0..191
                const int c4  = (idx & 7) * 4;      // 0..28
                float4 val = make_float4(0.f, 0.f, 0.f, 0.f);
                if (c4 < rem) {
                    if (row < 128) {
                        val = seg1
                          ? *(const float4*)(A1  + (size_t)(mBase + row) * lda1 + kA + c4)
                          : *(const float4*)(A2b + (size_t)(mBase + row) * ld2
                                             + (A2 ? kA + c4 : 0));
                    } else {
                        val = *(const float4*)(W + (size_t)(nBase + row - 128) * K + k0 + c4);
                    }
                }
                v[q] = val;
            }

            // ---- wait stage free (consumers done with chunk it-3) ----
            if (it >= NSTAGE) BAR_SYNC(4 + s);

            // ---- convert hi/lo + STS ----
            const unsigned stgB = sb + (unsigned)s * STG;
#pragma unroll
            for (int q = 0; q < 12; ++q) {
                const int idx = pt + q * 128;
                const int row = idx >> 3;
                const int cb  = (idx & 7) * 8;      // byte offset of 4 halfs
                const unsigned addr = (row < 128)
                    ? stgB + (unsigned)(row * PITCH + cb)
                    : stgB + BH_REL + (unsigned)((row - 128) * PITCH + cb);
                const unsigned loRel = (row < 128) ? ALO : BLO;
                const float4 x = v[q];
                __half2 h01 = __floats2half2_rn(x.x, x.y);
                __half2 h23 = __floats2half2_rn(x.z, x.w);
                float2 f01 = __half22float2(h01);
                float2 f23 = __half22float2(h23);
                __half2 l01 = __floats2half2_rn((x.x - f01.x) * LO_SCALE,
                                                (x.y - f01.y) * LO_SCALE);
                __half2 l23 = __floats2half2_rn((x.z - f23.x) * LO_SCALE,
                                                (x.w - f23.y) * LO_SCALE);
                unsigned uh0 = *(unsigned*)&h01, uh1 = *(unsigned*)&h23;
                unsigned ul0 = *(unsigned*)&l01, ul1 = *(unsigned*)&l23;
                asm volatile("st.shared.v2.b32 [%0], {%1,%2};"
                             :: "r"(addr), "r"(uh0), "r"(uh1) : "memory");
                asm volatile("st.shared.v2.b32 [%0], {%1,%2};"
                             :: "r"(addr + loRel), "r"(ul0), "r"(ul1) : "memory");
            }
            BAR_ARRIVE(1 + s);
            if (++s == NSTAGE) s = 0;
        }
        return;
    }

    // ======================= CONSUMER (warps 0-7) ===========================
    const int mW = (wid >> 1) * 32;        // 4 M-groups
    const int nW = (wid & 1) * 32;         // 2 N-groups

    float acc0[2][4][4];
    float acc1[2][4][4];
#pragma unroll
    for (int i = 0; i < 2; i++)
#pragma unroll
        for (int j = 0; j < 4; j++)
#pragma unroll
            for (int c = 0; c < 4; c++) { acc0[i][j][c] = 0.f; acc1[i][j][c] = 0.f; }

    const unsigned aOff = (unsigned)((mW + (lane & 15)) * PITCH + (lane >> 4) * 16);
    const unsigned bOff = BH_REL + (unsigned)((nW + (lane & 15)) * PITCH + (lane >> 4) * 16);

    int s = 0;
    for (int it = 0; it < nch; ++it) {
        BAR_SYNC(1 + s);
        const unsigned stgB = sb + (unsigned)s * STG;
        const unsigned aB = stgB + aOff;
        const unsigned bB = stgB + bOff;

#pragma unroll
        for (int kk = 0; kk < 2; ++kk) {
            unsigned bH[4][2], bL[4][2];
#pragma unroll
            for (int np = 0; np < 2; ++np) {
                const unsigned bd = bB + (unsigned)(np * 16 * PITCH + kk * 32);
                unsigned r0, r1, r2, r3;
                LDMX4(r0, r1, r2, r3, bd);
                bH[2 * np][0] = r0; bH[2 * np][1] = r2;
                bH[2 * np + 1][0] = r1; bH[2 * np + 1][1] = r3;
                LDMX4(r0, r1, r2, r3, bd + BLO);
                bL[2 * np][0] = r0; bL[2 * np][1] = r2;
                bL[2 * np + 1][0] = r1; bL[2 * np + 1][1] = r3;
            }
#pragma unroll
            for (int mt = 0; mt < 2; ++mt) {
                unsigned aH[4], aL[4];
                const unsigned ad = aB + (unsigned)(mt * 16 * PITCH + kk * 32);
                LDMX4(aH[0], aH[1], aH[2], aH[3], ad);
                LDMX4(aL[0], aL[1], aL[2], aL[3], ad + ALO);
#pragma unroll
                for (int nt = 0; nt < 4; ++nt)
                    MMA16816(acc0[mt][nt], aH, bH[nt][0], bH[nt][1]);
#pragma unroll
                for (int nt = 0; nt < 4; ++nt)
                    MMA16816(acc1[mt][nt], aH, bL[nt][0], bL[nt][1]);
#pragma unroll
                for (int nt = 0; nt < 4; ++nt)
                    MMA16816(acc1[mt][nt], aL, bH[nt][0], bH[nt][1]);
            }
        }
        BAR_ARRIVE(4 + s);
        if (++s == NSTAGE) s = 0;
    }

    // ---- epilogue: C = acc0 + acc1/2048 (+bias) ----
    const int g = lane >> 2, t = lane & 3;
#pragma unroll
    for (int mt = 0; mt < 2; ++mt) {
#pragma unroll
        for (int nt = 0; nt < 4; ++nt) {
            const int row = mBase + mW + mt * 16 + g;
            const int col = nBase + nW + nt * 8 + t * 2;
            float bx = 0.f, by = 0.f;
            if (bias) { bx = bias[col]; by = bias[col + 1]; }
            float2 o0, o1;
            o0.x = fmaf(acc1[mt][nt][0], LO_UNSCALE, acc0[mt][nt][0]) + bx;
            o0.y = fmaf(acc1[mt][nt][1], LO_UNSCALE, acc0[mt][nt][1]) + by;
            o1.x = fmaf(acc1[mt][nt][2], LO_UNSCALE, acc0[mt][nt][2]) + bx;
            o1.y = fmaf(acc1[mt][nt][3], LO_UNSCALE, acc0[mt][nt][3]) + by;
            *(float2*)(C + (size_t)row * ldc + col)       = o0;
            *(float2*)(C + (size_t)(row + 8) * ldc + col) = o1;
        }
    }
}

// ---------------------------------------------------------------------------
// LayerNorm(eps=1e-3) + SiLU (rows of 512; 128 threads/row)
// ---------------------------------------------------------------------------
__device__ __forceinline__ float block_reduce_128(float v, float* sm)
{
#pragma unroll
    for (int o = 16; o > 0; o >>= 1) v += __shfl_xor_sync(0xffffffffu, v, o);
    int w = threadIdx.x >> 5;
    if ((threadIdx.x & 31) == 0) sm[w] = v;
    __syncthreads();
    float r = sm[0] + sm[1] + sm[2] + sm[3];
    __syncthreads();
    return r;
}

__global__ void ln_silu_kernel(const float* __restrict__ in, float* __restrict__ out,
                               const float* __restrict__ g, const float* __restrict__ bb)
{
    __shared__ float sm[4];
    const int row = blockIdx.x;
    const float4 v = ((const float4*)(in + (size_t)row * HID))[threadIdx.x];
    float s = v.x + v.y + v.z + v.w;
    float mean = block_reduce_128(s, sm) * (1.f / HID);
    float dx = v.x - mean, dy = v.y - mean, dz = v.z - mean, dw = v.w - mean;
    float q = dx * dx + dy * dy + dz * dz + dw * dw;
    float var = block_reduce_128(q, sm) * (1.f / HID);
    float rs = rsqrtf(var + LNEPS);
    float4 gg = ((const float4*)g)[threadIdx.x];
    float4 bv = ((const float4*)bb)[threadIdx.x];
    float t0 = dx * rs * gg.x + bv.x;
    float t1 = dy * rs * gg.y + bv.y;
    float t2 = dz * rs * gg.z + bv.z;
    float t3 = dw * rs * gg.w + bv.w;
    float4 o;
    o.x = t0 / (1.f + expf(-t0));
    o.y = t1 / (1.f + expf(-t1));
    o.z = t2 / (1.f + expf(-t2));
    o.w = t3 / (1.f + expf(-t3));
    ((float4*)(out + (size_t)row * HID))[threadIdx.x] = o;
}

// ---------------------------------------------------------------------------
// GRU gates (torch order r,z,n) -> deter into d_out cols [0,512)
// ---------------------------------------------------------------------------
__device__ __forceinline__ float sigmoidf_(float x) { return 1.f / (1.f + expf(-x)); }

__global__ void gru_kernel(const float* __restrict__ gi, const float* __restrict__ gh,
                           const float* __restrict__ deter_old, float* __restrict__ out)
{
    int idx = blockIdx.x * blockDim.x + threadIdx.x;
    int b = idx >> 9;
    int h = idx & 511;
    size_t base = (size_t)b * NGATE;
    float r = sigmoidf_(gi[base + h]        + gh[base + h]);
    float z = sigmoidf_(gi[base + 512 + h]  + gh[base + 512 + h]);
    float n = tanhf    (gi[base + 1024 + h] + r * gh[base + 1024 + h]);
    float d = (1.f - z) * n + z * deter_old[(size_t)b * NDETER + h];
    out[(size_t)b * OUTW + h] = d;
}

// ---------------------------------------------------------------------------
// Per-group-32 softmax -> unimix -> argmax one-hot (d_out cols [1536,2560))
// ---------------------------------------------------------------------------
__global__ void softmax_onehot_kernel(float* __restrict__ out)
{
    int gw   = (blockIdx.x * blockDim.x + threadIdx.x) >> 5;
    int lane = threadIdx.x & 31;
    int b    = gw >> 5;
    int grp  = gw & 31;
    float* row = out + (size_t)b * OUTW;
    float l = row[512 + grp * 32 + lane];
    float m = l;
#pragma unroll
    for (int o = 16; o > 0; o >>= 1) m = fmaxf(m, __shfl_xor_sync(0xffffffffu, m, o));
    float e = expf(l - m);
    float s = e;
#pragma unroll
    for (int o = 16; o > 0; o >>= 1) s += __shfl_xor_sync(0xffffffffu, s, o);
    float p = (1.f - UNIMIX) * (e / s) + UNIMIX / 32.f;
    float bp = p; int bi = lane;
#pragma unroll
    for (int o = 16; o > 0; o >>= 1) {
        float op = __shfl_xor_sync(0xffffffffu, bp, o);
        int   oi = __shfl_xor_sync(0xffffffffu, bi, o);
        if (op > bp || (op == bp && oi < bi)) { bp = op; bi = oi; }
    }
    row[1536 + grp * 32 + lane] = (lane == bi) ? 1.f : 0.f;
}

// ---------------------------------------------------------------------------
// Launch
// ---------------------------------------------------------------------------
extern "C" void kernel_launch(void* const* d_in, const int* in_sizes, int n_in,
                              void* d_out_, int out_size)
{
    const float* obs   = (const float*)d_in[0];
    const float* act   = (const float*)d_in[1];
    const float* stoch = (const float*)d_in[2];
    const float* deter = (const float*)d_in[3];
    const float* W_in  = (const float*)d_in[4];
    const float* gin   = (const float*)d_in[5];
    const float* bin   = (const float*)d_in[6];
    const float* W_ih  = (const float*)d_in[7];
    const float* W_hh  = (const float*)d_in[8];
    const float* b_ih  = (const float*)d_in[9];
    const float* b_hh  = (const float*)d_in[10];
    const float* W_obs = (const float*)d_in[11];
    const float* gobs  = (const float*)d_in[12];
    const float* bobs  = (const float*)d_in[13];
    const float* W_st  = (const float*)d_in[14];
    const float* b_st  = (const float*)d_in[15];
    float* out = (float*)d_out_;

    float *xbuf, *gi, *gh, *ybuf;
    cudaGetSymbolAddress((void**)&xbuf, g_xbuf);
    cudaGetSymbolAddress((void**)&gi,   g_gi);
    cudaGetSymbolAddress((void**)&gh,   g_gh);
    cudaGetSymbolAddress((void**)&ybuf, g_ybuf);

    cudaFuncSetAttribute(gemm_hmma, cudaFuncAttributeMaxDynamicSharedMemorySize, GEMM_SMEM);

    const int MT = B / 128;  // 128

    // 1) x_pre = [stoch | actions] @ W_in^T      (N=512, K=1084, K1=1024)
    gemm_hmma<<<dim3(HID / 64, MT), 384, GEMM_SMEM>>>(
        stoch, 1024, 1024, act, 60, W_in, nullptr, xbuf, HID, KIN);
    // 2) x = silu(LN(x_pre))
    ln_silu_kernel<<<B, 128>>>(xbuf, xbuf, gin, bin);
    // 3) gi = x @ W_ih^T + b_ih                  (N=1536, K=512)
    gemm_hmma<<<dim3(NGATE / 64, MT), 384, GEMM_SMEM>>>(
        xbuf, HID, HID, nullptr, 0, W_ih, b_ih, gi, NGATE, HID);
    // 4) gh = deter @ W_hh^T + b_hh
    gemm_hmma<<<dim3(NGATE / 64, MT), 384, GEMM_SMEM>>>(
        deter, NDETER, NDETER, nullptr, 0, W_hh, b_hh, gh, NGATE, NDETER);
    // 5) GRU -> deter_new in d_out[:, 0:512)
    gru_kernel<<<(B * NDETER) / 256, 256>>>(gi, gh, deter, out);
    // 6) y_pre = [deter_new | obs_enc] @ W_obs^T (N=512, K=5632, K1=512)
    gemm_hmma<<<dim3(HID / 64, MT), 384, GEMM_SMEM>>>(
        out, OUTW, NDETER, obs, 5120, W_obs, nullptr, ybuf, HID, KOBS);
    // 7) y = silu(LN(y_pre))
    ln_silu_kernel<<<B, 128>>>(ybuf, ybuf, gobs, bobs);
    // 8) logits = y @ W_stats^T + b_stats -> d_out[:, 512:1536)
    gemm_hmma<<<dim3(NSTATS / 64, MT), 384, GEMM_SMEM>>>(
        ybuf, HID, HID, nullptr, 0, W_st, b_st, out + 512, OUTW, HID);
    // 9) softmax/unimix/argmax one-hot -> d_out[:, 1536:2560)
    softmax_onehot_kernel<<<(B * 32 * 32) / 256, 256>>>(out);
}

// round 13
// speedup vs baseline: 1.3368x; 1.3368x over previous
#include <cuda_runtime.h>
#include <cuda_fp16.h>
#include <math.h>

// ---------------------------------------------------------------------------
// Problem constants
// ---------------------------------------------------------------------------
#define B       16384
#define HID     512
#define NDETER  512
#define NGATE   1536
#define KIN     1084
#define KOBS    5632
#define NSTATS  1024
#define OUTW    2560
#define LNEPS   1e-3f
#define UNIMIX  0.01f
#define LO_SCALE    2048.0f
#define LO_UNSCALE  (1.0f / 2048.0f)

// ---------------------------------------------------------------------------
// Scratch (device globals; no runtime allocation allowed)
// ---------------------------------------------------------------------------
__device__ float g_xbuf[(size_t)B * HID];
__device__ float g_gi  [(size_t)B * NGATE];
__device__ float g_gh  [(size_t)B * NGATE];
__device__ float g_ybuf[(size_t)B * HID];

// ---------------------------------------------------------------------------
// Helpers
// ---------------------------------------------------------------------------
__device__ __forceinline__ unsigned smem_u32(const void* p) {
    unsigned a;
    asm("{ .reg .u64 t; cvta.to.shared.u64 t, %1; cvt.u32.u64 %0, t; }"
        : "=r"(a) : "l"(p));
    return a;
}

#define MMA16816(acc, a, b0v, b1v)                                            \
    asm volatile(                                                             \
        "mma.sync.aligned.m16n8k16.row.col.f32.f16.f16.f32 "                  \
        "{%0,%1,%2,%3}, {%4,%5,%6,%7}, {%8,%9}, {%0,%1,%2,%3};"               \
        : "+f"((acc)[0]), "+f"((acc)[1]), "+f"((acc)[2]), "+f"((acc)[3])      \
        : "r"((a)[0]), "r"((a)[1]), "r"((a)[2]), "r"((a)[3]),                 \
          "r"(b0v), "r"(b1v))

#define LDMX4(r0, r1, r2, r3, addr)                                           \
    asm volatile("ldmatrix.sync.aligned.m8n8.x4.shared.b16 {%0,%1,%2,%3}, [%4];" \
        : "=r"(r0), "=r"(r1), "=r"(r2), "=r"(r3) : "r"(addr))

// ---------------------------------------------------------------------------
// fp16-split (Ootomo, scaled residual) HMMA GEMM — ROUND-8 BIT-EXACT:
//   C[M,N] = A[M,K] * W[N,K]^T (+ bias)
// x = hi + lo/2048 (fp16).  acc0 += hi*hi;  acc1 += hi*lo + lo*hi;
// C = acc0 + acc1/2048.  fp32 accumulators everywhere.
// CTA tile 128x128, K-chunk 32 fp32, 16 warps (4Mx4N), warp tile 32x32.
// 2-stage smem pipeline, stage layout AH@0, AL@10240, BH@20480, BL@30720,
// pitch 80B, stage stride 64KB.
// NUMERICS FROZEN: rel_err must be exactly 9.778108e-4 (2 argmax flips).
// ---------------------------------------------------------------------------
#define BKF     32
#define PITCH   80
#define AL_REL  10240u
#define BH_REL  20480u
#define STAGE_STRIDE 65536u
#define GEMM_SMEM (2 * 65536)

__global__ __launch_bounds__(512, 1)
void gemm_hmma(const float* __restrict__ A1, int lda1, int K1,
               const float* __restrict__ A2, int lda2,
               const float* __restrict__ W, const float* __restrict__ bias,
               float* __restrict__ C, int ldc, int K)
{
    extern __shared__ char smem[];
    const unsigned sb = smem_u32(smem);
    const int tid  = threadIdx.x;
    const int lane = tid & 31;
    const int wid  = tid >> 5;              // 0..15
    const int mW   = (wid >> 2) * 32;       // 4 M-groups
    const int nW   = (wid & 3) * 32;        // 4 N-groups
    const int mBase = blockIdx.y * 128;
    const int nBase = blockIdx.x * 128;

    float acc0[2][4][4];   // hi*hi
    float acc1[2][4][4];   // hi*lo + lo*hi (scaled by 2048)
#pragma unroll
    for (int i = 0; i < 2; i++)
#pragma unroll
        for (int j = 0; j < 4; j++)
#pragma unroll
            for (int c = 0; c < 4; c++) { acc0[i][j][c] = 0.f; acc1[i][j][c] = 0.f; }

    // ---- hoisted global pointers ----
    const int rowq = tid >> 3;             // 0..63
    const int c4b  = (tid & 7) * 4;        // k element offset
    const float* A2b = A2 ? A2 : A1;
    const int    ld2 = A2 ? lda2 : 0;
    const int    c4b2 = A2 ? c4b : 0;
    const float* pA1[2]; const float* pA2[2]; const float* pW[2];
#pragma unroll
    for (int q = 0; q < 2; ++q) {
        const int row = q * 64 + rowq;
        pA1[q] = A1  + (size_t)(mBase + row) * lda1 + c4b;
        pA2[q] = A2b + (size_t)(mBase + row) * ld2  + c4b2;
        pW[q]  = W   + (size_t)(nBase + row) * K    + c4b;
    }

    // ---- hoisted smem bases ----
    const unsigned stsBase0 = sb + (unsigned)(rowq * PITCH + (tid & 7) * 8);
    const unsigned stsBase1 = stsBase0 + STAGE_STRIDE;
    const unsigned aBase0 = sb + (unsigned)((mW + (lane & 15)) * PITCH + (lane >> 4) * 16);
    const unsigned aBase1 = aBase0 + STAGE_STRIDE;
    const unsigned bBase0 = sb + BH_REL
                          + (unsigned)((nW + (lane & 15)) * PITCH + (lane >> 4) * 16);
    const unsigned bBase1 = bBase0 + STAGE_STRIDE;

    const int nch = (K + BKF - 1) / BKF;

    float4 v[4];
    auto ldg_chunk = [&](int k0) {
        const bool seg1 = (k0 < K1);
        const int  kA   = seg1 ? k0 : k0 - K1;
        if (k0 + BKF <= K) {
#pragma unroll
            for (int q = 0; q < 2; ++q) {
                v[q]     = *(const float4*)((seg1 ? pA1[q] : pA2[q]) + kA);
                v[q + 2] = *(const float4*)(pW[q] + k0);
            }
        } else {
            const int rem = K - k0;
#pragma unroll
            for (int q = 0; q < 2; ++q) {
                float4 z = make_float4(0.f, 0.f, 0.f, 0.f);
                v[q]     = (c4b < rem) ? *(const float4*)((seg1 ? pA1[q] : pA2[q]) + kA) : z;
                v[q + 2] = (c4b < rem) ? *(const float4*)(pW[q] + k0) : z;
            }
        }
    };
    auto sts_chunk = [&](unsigned stsB) {
#pragma unroll
        for (int q = 0; q < 4; ++q) {
            const unsigned addr = stsB + (unsigned)((q & 1) * 64 * PITCH)
                                + (q < 2 ? 0u : BH_REL);
            const float4 x = v[q];
            __half2 h01 = __floats2half2_rn(x.x, x.y);
            __half2 h23 = __floats2half2_rn(x.z, x.w);
            float2 f01 = __half22float2(h01);
            float2 f23 = __half22float2(h23);
            __half2 l01 = __floats2half2_rn((x.x - f01.x) * LO_SCALE,
                                            (x.y - f01.y) * LO_SCALE);
            __half2 l23 = __floats2half2_rn((x.z - f23.x) * LO_SCALE,
                                            (x.w - f23.y) * LO_SCALE);
            unsigned uh0 = *(unsigned*)&h01, uh1 = *(unsigned*)&h23;
            unsigned ul0 = *(unsigned*)&l01, ul1 = *(unsigned*)&l23;
            asm volatile("st.shared.v2.b32 [%0], {%1,%2};"
                         :: "r"(addr), "r"(uh0), "r"(uh1) : "memory");
            asm volatile("st.shared.v2.b32 [%0], {%1,%2};"
                         :: "r"(addr + AL_REL), "r"(ul0), "r"(ul1) : "memory");
        }
    };

    ldg_chunk(0);
    sts_chunk(stsBase0);
    __syncthreads();

    for (int it = 0; it < nch; ++it) {
        const unsigned aB = (it & 1) ? aBase1 : aBase0;
        const unsigned bB = (it & 1) ? bBase1 : bBase0;
        if (it + 1 < nch) ldg_chunk((it + 1) * BKF);

#pragma unroll
        for (int kk = 0; kk < 2; ++kk) {
            // --- B fragments for this k16 (4 n8-tiles, hi+lo) ---
            unsigned bH[4][2], bL[4][2];
#pragma unroll
            for (int np = 0; np < 2; ++np) {
                const unsigned bd = bB + (unsigned)(np * 16 * PITCH + kk * 32);
                unsigned r0, r1, r2, r3;
                LDMX4(r0, r1, r2, r3, bd);
                bH[2 * np][0] = r0; bH[2 * np][1] = r2;
                bH[2 * np + 1][0] = r1; bH[2 * np + 1][1] = r3;
                LDMX4(r0, r1, r2, r3, bd + AL_REL);
                bL[2 * np][0] = r0; bL[2 * np][1] = r2;
                bL[2 * np + 1][0] = r1; bL[2 * np + 1][1] = r3;
            }
            // --- 2 m16-tiles: load A frags then 3 MMA passes ---
#pragma unroll
            for (int mt = 0; mt < 2; ++mt) {
                unsigned aH[4], aL[4];
                const unsigned ad = aB + (unsigned)(mt * 16 * PITCH + kk * 32);
                LDMX4(aH[0], aH[1], aH[2], aH[3], ad);
                LDMX4(aL[0], aL[1], aL[2], aL[3], ad + AL_REL);
#pragma unroll
                for (int nt = 0; nt < 4; ++nt)
                    MMA16816(acc0[mt][nt], aH, bH[nt][0], bH[nt][1]);
#pragma unroll
                for (int nt = 0; nt < 4; ++nt)
                    MMA16816(acc1[mt][nt], aH, bL[nt][0], bL[nt][1]);
#pragma unroll
                for (int nt = 0; nt < 4; ++nt)
                    MMA16816(acc1[mt][nt], aL, bH[nt][0], bH[nt][1]);
            }
        }

        if (it + 1 < nch) sts_chunk((it & 1) ? stsBase0 : stsBase1);
        __syncthreads();
    }

    // ---- epilogue: C = acc0 + acc1/2048 (+bias) ----
    const int g = lane >> 2, t = lane & 3;
#pragma unroll
    for (int mt = 0; mt < 2; ++mt) {
#pragma unroll
        for (int nt = 0; nt < 4; ++nt) {
            const int row = mBase + mW + mt * 16 + g;
            const int col = nBase + nW + nt * 8 + t * 2;
            float bx = 0.f, by = 0.f;
            if (bias) { bx = bias[col]; by = bias[col + 1]; }
            float2 o0, o1;
            o0.x = fmaf(acc1[mt][nt][0], LO_UNSCALE, acc0[mt][nt][0]) + bx;
            o0.y = fmaf(acc1[mt][nt][1], LO_UNSCALE, acc0[mt][nt][1]) + by;
            o1.x = fmaf(acc1[mt][nt][2], LO_UNSCALE, acc0[mt][nt][2]) + bx;
            o1.y = fmaf(acc1[mt][nt][3], LO_UNSCALE, acc0[mt][nt][3]) + by;
            *(float2*)(C + (size_t)row * ldc + col)       = o0;
            *(float2*)(C + (size_t)(row + 8) * ldc + col) = o1;
        }
    }
}

// ---------------------------------------------------------------------------
// LayerNorm(eps=1e-3) + SiLU (rows of 512; 128 threads/row)
// ---------------------------------------------------------------------------
__device__ __forceinline__ float block_reduce_128(float v, float* sm)
{
#pragma unroll
    for (int o = 16; o > 0; o >>= 1) v += __shfl_xor_sync(0xffffffffu, v, o);
    int w = threadIdx.x >> 5;
    if ((threadIdx.x & 31) == 0) sm[w] = v;
    __syncthreads();
    float r = sm[0] + sm[1] + sm[2] + sm[3];
    __syncthreads();
    return r;
}

__global__ void ln_silu_kernel(const float* __restrict__ in, float* __restrict__ out,
                               const float* __restrict__ g, const float* __restrict__ bb)
{
    __shared__ float sm[4];
    const int row = blockIdx.x;
    const float4 v = ((const float4*)(in + (size_t)row * HID))[threadIdx.x];
    float s = v.x + v.y + v.z + v.w;
    float mean = block_reduce_128(s, sm) * (1.f / HID);
    float dx = v.x - mean, dy = v.y - mean, dz = v.z - mean, dw = v.w - mean;
    float q = dx * dx + dy * dy + dz * dz + dw * dw;
    float var = block_reduce_128(q, sm) * (1.f / HID);
    float rs = rsqrtf(var + LNEPS);
    float4 gg = ((const float4*)g)[threadIdx.x];
    float4 bv = ((const float4*)bb)[threadIdx.x];
    float t0 = dx * rs * gg.x + bv.x;
    float t1 = dy * rs * gg.y + bv.y;
    float t2 = dz * rs * gg.z + bv.z;
    float t3 = dw * rs * gg.w + bv.w;
    float4 o;
    o.x = t0 / (1.f + expf(-t0));
    o.y = t1 / (1.f + expf(-t1));
    o.z = t2 / (1.f + expf(-t2));
    o.w = t3 / (1.f + expf(-t3));
    ((float4*)(out + (size_t)row * HID))[threadIdx.x] = o;
}

// ---------------------------------------------------------------------------
// GRU gates (torch order r,z,n) -> deter into d_out cols [0,512)
// float4-vectorized (4 h per thread); per-element math identical to the
// scalar round-8 version -> bit-identical output.
// ---------------------------------------------------------------------------
__device__ __forceinline__ float sigmoidf_(float x) { return 1.f / (1.f + expf(-x)); }

__global__ void gru_kernel_v4(const float* __restrict__ gi, const float* __restrict__ gh,
                              const float* __restrict__ deter_old, float* __restrict__ out)
{
    int idx = blockIdx.x * blockDim.x + threadIdx.x;   // over B*512/4
    int b  = idx >> 7;           // 512/4 = 128 quads per row
    int hq = idx & 127;
    size_t base = (size_t)b * NGATE + hq * 4;
    float4 gir = *(const float4*)(gi + base);
    float4 giz = *(const float4*)(gi + base + 512);
    float4 gin = *(const float4*)(gi + base + 1024);
    float4 ghr = *(const float4*)(gh + base);
    float4 ghz = *(const float4*)(gh + base + 512);
    float4 ghn = *(const float4*)(gh + base + 1024);
    float4 dv  = *(const float4*)(deter_old + (size_t)b * NDETER + hq * 4);
    float4 o;
    {
        float r = sigmoidf_(gir.x + ghr.x);
        float z = sigmoidf_(giz.x + ghz.x);
        float n = tanhf(gin.x + r * ghn.x);
        o.x = (1.f - z) * n + z * dv.x;
    }
    {
        float r = sigmoidf_(gir.y + ghr.y);
        float z = sigmoidf_(giz.y + ghz.y);
        float n = tanhf(gin.y + r * ghn.y);
        o.y = (1.f - z) * n + z * dv.y;
    }
    {
        float r = sigmoidf_(gir.z + ghr.z);
        float z = sigmoidf_(giz.z + ghz.z);
        float n = tanhf(gin.z + r * ghn.z);
        o.z = (1.f - z) * n + z * dv.z;
    }
    {
        float r = sigmoidf_(gir.w + ghr.w);
        float z = sigmoidf_(giz.w + ghz.w);
        float n = tanhf(gin.w + r * ghn.w);
        o.w = (1.f - z) * n + z * dv.w;
    }
    *(float4*)(out + (size_t)b * OUTW + hq * 4) = o;
}

// ---------------------------------------------------------------------------
// Per-group-32 softmax -> unimix -> argmax one-hot (d_out cols [1536,2560))
// ---------------------------------------------------------------------------
__global__ void softmax_onehot_kernel(float* __restrict__ out)
{
    int gw   = (blockIdx.x * blockDim.x + threadIdx.x) >> 5;
    int lane = threadIdx.x & 31;
    int b    = gw >> 5;
    int grp  = gw & 31;
    float* row = out + (size_t)b * OUTW;
    float l = row[512 + grp * 32 + lane];
    float m = l;
#pragma unroll
    for (int o = 16; o > 0; o >>= 1) m = fmaxf(m, __shfl_xor_sync(0xffffffffu, m, o));
    float e = expf(l - m);
    float s = e;
#pragma unroll
    for (int o = 16; o > 0; o >>= 1) s += __shfl_xor_sync(0xffffffffu, s, o);
    float p = (1.f - UNIMIX) * (e / s) + UNIMIX / 32.f;
    float bp = p; int bi = lane;
#pragma unroll
    for (int o = 16; o > 0; o >>= 1) {
        float op = __shfl_xor_sync(0xffffffffu, bp, o);
        int   oi = __shfl_xor_sync(0xffffffffu, bi, o);
        if (op > bp || (op == bp && oi < bi)) { bp = op; bi = oi; }
    }
    row[1536 + grp * 32 + lane] = (lane == bi) ? 1.f : 0.f;
}

// ---------------------------------------------------------------------------
// Launch
// ---------------------------------------------------------------------------
extern "C" void kernel_launch(void* const* d_in, const int* in_sizes, int n_in,
                              void* d_out_, int out_size)
{
    const float* obs   = (const float*)d_in[0];
    const float* act   = (const float*)d_in[1];
    const float* stoch = (const float*)d_in[2];
    const float* deter = (const float*)d_in[3];
    const float* W_in  = (const float*)d_in[4];
    const float* gin   = (const float*)d_in[5];
    const float* bin   = (const float*)d_in[6];
    const float* W_ih  = (const float*)d_in[7];
    const float* W_hh  = (const float*)d_in[8];
    const float* b_ih  = (const float*)d_in[9];
    const float* b_hh  = (const float*)d_in[10];
    const float* W_obs = (const float*)d_in[11];
    const float* gobs  = (const float*)d_in[12];
    const float* bobs  = (const float*)d_in[13];
    const float* W_st  = (const float*)d_in[14];
    const float* b_st  = (const float*)d_in[15];
    float* out = (float*)d_out_;

    float *xbuf, *gi, *gh, *ybuf;
    cudaGetSymbolAddress((void**)&xbuf, g_xbuf);
    cudaGetSymbolAddress((void**)&gi,   g_gi);
    cudaGetSymbolAddress((void**)&gh,   g_gh);
    cudaGetSymbolAddress((void**)&ybuf, g_ybuf);

    cudaFuncSetAttribute(gemm_hmma, cudaFuncAttributeMaxDynamicSharedMemorySize, GEMM_SMEM);

    const int MT = B / 128;  // 128

    // 1) x_pre = [stoch | actions] @ W_in^T      (N=512, K=1084, K1=1024)
    gemm_hmma<<<dim3(HID / 128, MT), 512, GEMM_SMEM>>>(
        stoch, 1024, 1024, act, 60, W_in, nullptr, xbuf, HID, KIN);
    // 2) x = silu(LN(x_pre))
    ln_silu_kernel<<<B, 128>>>(xbuf, xbuf, gin, bin);
    // 3) gi = x @ W_ih^T + b_ih                  (N=1536, K=512)
    gemm_hmma<<<dim3(NGATE / 128, MT), 512, GEMM_SMEM>>>(
        xbuf, HID, HID, nullptr, 0, W_ih, b_ih, gi, NGATE, HID);
    // 4) gh = deter @ W_hh^T + b_hh
    gemm_hmma<<<dim3(NGATE / 128, MT), 512, GEMM_SMEM>>>(
        deter, NDETER, NDETER, nullptr, 0, W_hh, b_hh, gh, NGATE, NDETER);
    // 5) GRU -> deter_new in d_out[:, 0:512)   (vectorized, bit-identical)
    gru_kernel_v4<<<(B * NDETER / 4) / 256, 256>>>(gi, gh, deter, out);
    // 6) y_pre = [deter_new | obs_enc] @ W_obs^T (N=512, K=5632, K1=512)
    gemm_hmma<<<dim3(HID / 128, MT), 512, GEMM_SMEM>>>(
        out, OUTW, NDETER, obs, 5120, W_obs, nullptr, ybuf, HID, KOBS);
    // 7) y = silu(LN(y_pre))
    ln_silu_kernel<<<B, 128>>>(ybuf, ybuf, gobs, bobs);
    // 8) logits = y @ W_stats^T + b_stats -> d_out[:, 512:1536)
    gemm_hmma<<<dim3(NSTATS / 128, MT), 512, GEMM_SMEM>>>(
        ybuf, HID, HID, nullptr, 0, W_st, b_st, out + 512, OUTW, HID);
    // 9) softmax/unimix/argmax one-hot -> d_out[:, 1536:2560)
    softmax_onehot_kernel<<<(B * 32 * 32) / 256, 256>>>(out);
}

// round 14
// speedup vs baseline: 1.3510x; 1.0106x over previous
#include <cuda_runtime.h>
#include <cuda_fp16.h>
#include <math.h>

// ---------------------------------------------------------------------------
// Problem constants
// ---------------------------------------------------------------------------
#define B       16384
#define HID     512
#define NDETER  512
#define NGATE   1536
#define KIN     1084
#define KOBS    5632
#define NSTATS  1024
#define OUTW    2560
#define LNEPS   1e-3f
#define UNIMIX  0.01f
#define LO_SCALE    2048.0f
#define LO_UNSCALE  (1.0f / 2048.0f)

// ---------------------------------------------------------------------------
// Scratch (device globals; no runtime allocation allowed)
// ---------------------------------------------------------------------------
__device__ float g_xbuf[(size_t)B * HID];
__device__ float g_gi  [(size_t)B * NGATE];
__device__ float g_gh  [(size_t)B * NGATE];
__device__ float g_ybuf[(size_t)B * HID];

// ---------------------------------------------------------------------------
// Helpers
// ---------------------------------------------------------------------------
__device__ __forceinline__ unsigned smem_u32(const void* p) {
    unsigned a;
    asm("{ .reg .u64 t; cvta.to.shared.u64 t, %1; cvt.u32.u64 %0, t; }"
        : "=r"(a) : "l"(p));
    return a;
}

#define MMA16816(acc, a, b0v, b1v)                                            \
    asm volatile(                                                             \
        "mma.sync.aligned.m16n8k16.row.col.f32.f16.f16.f32 "                  \
        "{%0,%1,%2,%3}, {%4,%5,%6,%7}, {%8,%9}, {%0,%1,%2,%3};"               \
        : "+f"((acc)[0]), "+f"((acc)[1]), "+f"((acc)[2]), "+f"((acc)[3])      \
        : "r"((a)[0]), "r"((a)[1]), "r"((a)[2]), "r"((a)[3]),                 \
          "r"(b0v), "r"(b1v))

#define LDMX4(r0, r1, r2, r3, addr)                                           \
    asm volatile("ldmatrix.sync.aligned.m8n8.x4.shared.b16 {%0,%1,%2,%3}, [%4];" \
        : "=r"(r0), "=r"(r1), "=r"(r2), "=r"(r3) : "r"(addr))

// ---------------------------------------------------------------------------
// fp16-split (Ootomo, scaled residual) HMMA GEMM body — ROUND-8 BIT-EXACT:
//   C[M,N] = A[M,K] * W[N,K]^T (+ bias)
// x = hi + lo/2048 (fp16).  acc0 += hi*hi;  acc1 += hi*lo + lo*hi;
// C = acc0 + acc1/2048.  fp32 accumulators everywhere.
// CTA tile 128x128, K-chunk 32 fp32, 16 warps (4Mx4N), warp tile 32x32.
// 2-stage smem pipeline: AH@0, AL@10240, BH@20480, BL@30720, pitch 80B,
// stage stride 64KB.
// NUMERICS FROZEN: per-output-element op sequence must not change
// (rel_err must be exactly 9.778108e-4).  M/N tile assignment (mBase/nBase)
// does not enter any floating-point op -> grid packing is free.
// ---------------------------------------------------------------------------
#define BKF     32
#define PITCH   80
#define AL_REL  10240u
#define BH_REL  20480u
#define STAGE_STRIDE 65536u
#define GEMM_SMEM (2 * 65536)

__device__ __forceinline__
void gemm_body(const float* __restrict__ A1, int lda1, int K1,
               const float* __restrict__ A2, int lda2,
               const float* __restrict__ W, const float* __restrict__ bias,
               float* __restrict__ C, int ldc, int K,
               int mBase, int nBase, char* smem)
{
    const unsigned sb = smem_u32(smem);
    const int tid  = threadIdx.x;
    const int lane = tid & 31;
    const int wid  = tid >> 5;              // 0..15
    const int mW   = (wid >> 2) * 32;       // 4 M-groups
    const int nW   = (wid & 3) * 32;        // 4 N-groups

    float acc0[2][4][4];   // hi*hi
    float acc1[2][4][4];   // hi*lo + lo*hi (scaled by 2048)
#pragma unroll
    for (int i = 0; i < 2; i++)
#pragma unroll
        for (int j = 0; j < 4; j++)
#pragma unroll
            for (int c = 0; c < 4; c++) { acc0[i][j][c] = 0.f; acc1[i][j][c] = 0.f; }

    // ---- hoisted global pointers ----
    const int rowq = tid >> 3;             // 0..63
    const int c4b  = (tid & 7) * 4;        // k element offset
    const float* A2b = A2 ? A2 : A1;
    const int    ld2 = A2 ? lda2 : 0;
    const int    c4b2 = A2 ? c4b : 0;
    const float* pA1[2]; const float* pA2[2]; const float* pW[2];
#pragma unroll
    for (int q = 0; q < 2; ++q) {
        const int row = q * 64 + rowq;
        pA1[q] = A1  + (size_t)(mBase + row) * lda1 + c4b;
        pA2[q] = A2b + (size_t)(mBase + row) * ld2  + c4b2;
        pW[q]  = W   + (size_t)(nBase + row) * K    + c4b;
    }

    // ---- hoisted smem bases ----
    const unsigned stsBase0 = sb + (unsigned)(rowq * PITCH + (tid & 7) * 8);
    const unsigned stsBase1 = stsBase0 + STAGE_STRIDE;
    const unsigned aBase0 = sb + (unsigned)((mW + (lane & 15)) * PITCH + (lane >> 4) * 16);
    const unsigned aBase1 = aBase0 + STAGE_STRIDE;
    const unsigned bBase0 = sb + BH_REL
                          + (unsigned)((nW + (lane & 15)) * PITCH + (lane >> 4) * 16);
    const unsigned bBase1 = bBase0 + STAGE_STRIDE;

    const int nch = (K + BKF - 1) / BKF;

    float4 v[4];
    auto ldg_chunk = [&](int k0) {
        const bool seg1 = (k0 < K1);
        const int  kA   = seg1 ? k0 : k0 - K1;
        if (k0 + BKF <= K) {
#pragma unroll
            for (int q = 0; q < 2; ++q) {
                v[q]     = *(const float4*)((seg1 ? pA1[q] : pA2[q]) + kA);
                v[q + 2] = *(const float4*)(pW[q] + k0);
            }
        } else {
            const int rem = K - k0;
#pragma unroll
            for (int q = 0; q < 2; ++q) {
                float4 z = make_float4(0.f, 0.f, 0.f, 0.f);
                v[q]     = (c4b < rem) ? *(const float4*)((seg1 ? pA1[q] : pA2[q]) + kA) : z;
                v[q + 2] = (c4b < rem) ? *(const float4*)(pW[q] + k0) : z;
            }
        }
    };
    auto sts_chunk = [&](unsigned stsB) {
#pragma unroll
        for (int q = 0; q < 4; ++q) {
            const unsigned addr = stsB + (unsigned)((q & 1) * 64 * PITCH)
                                + (q < 2 ? 0u : BH_REL);
            const float4 x = v[q];
            __half2 h01 = __floats2half2_rn(x.x, x.y);
            __half2 h23 = __floats2half2_rn(x.z, x.w);
            float2 f01 = __half22float2(h01);
            float2 f23 = __half22float2(h23);
            __half2 l01 = __floats2half2_rn((x.x - f01.x) * LO_SCALE,
                                            (x.y - f01.y) * LO_SCALE);
            __half2 l23 = __floats2half2_rn((x.z - f23.x) * LO_SCALE,
                                            (x.w - f23.y) * LO_SCALE);
            unsigned uh0 = *(unsigned*)&h01, uh1 = *(unsigned*)&h23;
            unsigned ul0 = *(unsigned*)&l01, ul1 = *(unsigned*)&l23;
            asm volatile("st.shared.v2.b32 [%0], {%1,%2};"
                         :: "r"(addr), "r"(uh0), "r"(uh1) : "memory");
            asm volatile("st.shared.v2.b32 [%0], {%1,%2};"
                         :: "r"(addr + AL_REL), "r"(ul0), "r"(ul1) : "memory");
        }
    };

    ldg_chunk(0);
    sts_chunk(stsBase0);
    __syncthreads();

    for (int it = 0; it < nch; ++it) {
        const unsigned aB = (it & 1) ? aBase1 : aBase0;
        const unsigned bB = (it & 1) ? bBase1 : bBase0;
        if (it + 1 < nch) ldg_chunk((it + 1) * BKF);

#pragma unroll
        for (int kk = 0; kk < 2; ++kk) {
            unsigned bH[4][2], bL[4][2];
#pragma unroll
            for (int np = 0; np < 2; ++np) {
                const unsigned bd = bB + (unsigned)(np * 16 * PITCH + kk * 32);
                unsigned r0, r1, r2, r3;
                LDMX4(r0, r1, r2, r3, bd);
                bH[2 * np][0] = r0; bH[2 * np][1] = r2;
                bH[2 * np + 1][0] = r1; bH[2 * np + 1][1] = r3;
                LDMX4(r0, r1, r2, r3, bd + AL_REL);
                bL[2 * np][0] = r0; bL[2 * np][1] = r2;
                bL[2 * np + 1][0] = r1; bL[2 * np + 1][1] = r3;
            }
#pragma unroll
            for (int mt = 0; mt < 2; ++mt) {
                unsigned aH[4], aL[4];
                const unsigned ad = aB + (unsigned)(mt * 16 * PITCH + kk * 32);
                LDMX4(aH[0], aH[1], aH[2], aH[3], ad);
                LDMX4(aL[0], aL[1], aL[2], aL[3], ad + AL_REL);
#pragma unroll
                for (int nt = 0; nt < 4; ++nt)
                    MMA16816(acc0[mt][nt], aH, bH[nt][0], bH[nt][1]);
#pragma unroll
                for (int nt = 0; nt < 4; ++nt)
                    MMA16816(acc1[mt][nt], aH, bL[nt][0], bL[nt][1]);
#pragma unroll
                for (int nt = 0; nt < 4; ++nt)
                    MMA16816(acc1[mt][nt], aL, bH[nt][0], bH[nt][1]);
            }
        }

        if (it + 1 < nch) sts_chunk((it & 1) ? stsBase0 : stsBase1);
        __syncthreads();
    }

    // ---- epilogue: C = acc0 + acc1/2048 (+bias) ----
    const int g = lane >> 2, t = lane & 3;
#pragma unroll
    for (int mt = 0; mt < 2; ++mt) {
#pragma unroll
        for (int nt = 0; nt < 4; ++nt) {
            const int row = mBase + mW + mt * 16 + g;
            const int col = nBase + nW + nt * 8 + t * 2;
            float bx = 0.f, by = 0.f;
            if (bias) { bx = bias[col]; by = bias[col + 1]; }
            float2 o0, o1;
            o0.x = fmaf(acc1[mt][nt][0], LO_UNSCALE, acc0[mt][nt][0]) + bx;
            o0.y = fmaf(acc1[mt][nt][1], LO_UNSCALE, acc0[mt][nt][1]) + by;
            o1.x = fmaf(acc1[mt][nt][2], LO_UNSCALE, acc0[mt][nt][2]) + bx;
            o1.y = fmaf(acc1[mt][nt][3], LO_UNSCALE, acc0[mt][nt][3]) + by;
            *(float2*)(C + (size_t)row * ldc + col)       = o0;
            *(float2*)(C + (size_t)(row + 8) * ldc + col) = o1;
        }
    }
}

// Standard single-GEMM wrapper (2D grid: x = N-tile, y = M-tile)
__global__ __launch_bounds__(512, 1)
void gemm_hmma(const float* __restrict__ A1, int lda1, int K1,
               const float* __restrict__ A2, int lda2,
               const float* __restrict__ W, const float* __restrict__ bias,
               float* __restrict__ C, int ldc, int K)
{
    extern __shared__ char smem[];
    gemm_body(A1, lda1, K1, A2, lda2, W, bias, C, ldc, K,
              blockIdx.y * 128, blockIdx.x * 128, smem);
}

// Fused G1 (x_pre) + G4 (gh) wrapper — 1D grid, long G1 CTAs first.
// G1: 512 CTAs (4 N-tiles x 128 M-tiles, K=1084), then G4: 1536 CTAs
// (12 N-tiles x 128 M-tiles, K=512). Independent outputs; per-element math
// identical to separate launches -> bit-identical.
__global__ __launch_bounds__(512, 1)
void gemm_dual(const float* __restrict__ stoch, const float* __restrict__ act,
               const float* __restrict__ W_in, float* __restrict__ xbuf,
               const float* __restrict__ deter, const float* __restrict__ W_hh,
               const float* __restrict__ b_hh, float* __restrict__ gh)
{
    extern __shared__ char smem[];
    const int bid = blockIdx.x;
    if (bid < 512) {
        // G1: x_pre = [stoch | act] @ W_in^T
        const int nB = (bid & 3) * 128;
        const int mB = (bid >> 2) * 128;
        gemm_body(stoch, 1024, 1024, act, 60, W_in, nullptr,
                  xbuf, HID, KIN, mB, nB, smem);
    } else {
        // G4: gh = deter @ W_hh^T + b_hh
        const int t  = bid - 512;
        const int nB = (t % 12) * 128;
        const int mB = (t / 12) * 128;
        gemm_body(deter, NDETER, NDETER, nullptr, 0, W_hh, b_hh,
                  gh, NGATE, NDETER, mB, nB, smem);
    }
}

// ---------------------------------------------------------------------------
// LayerNorm(eps=1e-3) + SiLU (rows of 512; 128 threads/row)
// ---------------------------------------------------------------------------
__device__ __forceinline__ float block_reduce_128(float v, float* sm)
{
#pragma unroll
    for (int o = 16; o > 0; o >>= 1) v += __shfl_xor_sync(0xffffffffu, v, o);
    int w = threadIdx.x >> 5;
    if ((threadIdx.x & 31) == 0) sm[w] = v;
    __syncthreads();
    float r = sm[0] + sm[1] + sm[2] + sm[3];
    __syncthreads();
    return r;
}

__global__ void ln_silu_kernel(const float* __restrict__ in, float* __restrict__ out,
                               const float* __restrict__ g, const float* __restrict__ bb)
{
    __shared__ float sm[4];
    const int row = blockIdx.x;
    const float4 v = ((const float4*)(in + (size_t)row * HID))[threadIdx.x];
    float s = v.x + v.y + v.z + v.w;
    float mean = block_reduce_128(s, sm) * (1.f / HID);
    float dx = v.x - mean, dy = v.y - mean, dz = v.z - mean, dw = v.w - mean;
    float q = dx * dx + dy * dy + dz * dz + dw * dw;
    float var = block_reduce_128(q, sm) * (1.f / HID);
    float rs = rsqrtf(var + LNEPS);
    float4 gg = ((const float4*)g)[threadIdx.x];
    float4 bv = ((const float4*)bb)[threadIdx.x];
    float t0 = dx * rs * gg.x + bv.x;
    float t1 = dy * rs * gg.y + bv.y;
    float t2 = dz * rs * gg.z + bv.z;
    float t3 = dw * rs * gg.w + bv.w;
    float4 o;
    o.x = t0 / (1.f + expf(-t0));
    o.y = t1 / (1.f + expf(-t1));
    o.z = t2 / (1.f + expf(-t2));
    o.w = t3 / (1.f + expf(-t3));
    ((float4*)(out + (size_t)row * HID))[threadIdx.x] = o;
}

// ---------------------------------------------------------------------------
// GRU gates (torch order r,z,n) -> deter into d_out cols [0,512)
// float4-vectorized; per-element math identical to scalar -> bit-identical.
// ---------------------------------------------------------------------------
__device__ __forceinline__ float sigmoidf_(float x) { return 1.f / (1.f + expf(-x)); }

__global__ void gru_kernel_v4(const float* __restrict__ gi, const float* __restrict__ gh,
                              const float* __restrict__ deter_old, float* __restrict__ out)
{
    int idx = blockIdx.x * blockDim.x + threadIdx.x;   // over B*512/4
    int b  = idx >> 7;           // 128 quads per row
    int hq = idx & 127;
    size_t base = (size_t)b * NGATE + hq * 4;
    float4 gir = *(const float4*)(gi + base);
    float4 giz = *(const float4*)(gi + base + 512);
    float4 gin = *(const float4*)(gi + base + 1024);
    float4 ghr = *(const float4*)(gh + base);
    float4 ghz = *(const float4*)(gh + base + 512);
    float4 ghn = *(const float4*)(gh + base + 1024);
    float4 dv  = *(const float4*)(deter_old + (size_t)b * NDETER + hq * 4);
    float4 o;
    {
        float r = sigmoidf_(gir.x + ghr.x);
        float z = sigmoidf_(giz.x + ghz.x);
        float n = tanhf(gin.x + r * ghn.x);
        o.x = (1.f - z) * n + z * dv.x;
    }
    {
        float r = sigmoidf_(gir.y + ghr.y);
        float z = sigmoidf_(giz.y + ghz.y);
        float n = tanhf(gin.y + r * ghn.y);
        o.y = (1.f - z) * n + z * dv.y;
    }
    {
        float r = sigmoidf_(gir.z + ghr.z);
        float z = sigmoidf_(giz.z + ghz.z);
        float n = tanhf(gin.z + r * ghn.z);
        o.z = (1.f - z) * n + z * dv.z;
    }
    {
        float r = sigmoidf_(gir.w + ghr.w);
        float z = sigmoidf_(giz.w + ghz.w);
        float n = tanhf(gin.w + r * ghn.w);
        o.w = (1.f - z) * n + z * dv.w;
    }
    *(float4*)(out + (size_t)b * OUTW + hq * 4) = o;
}

// ---------------------------------------------------------------------------
// Per-group-32 softmax -> unimix -> argmax one-hot (d_out cols [1536,2560))
// ---------------------------------------------------------------------------
__global__ void softmax_onehot_kernel(float* __restrict__ out)
{
    int gw   = (blockIdx.x * blockDim.x + threadIdx.x) >> 5;
    int lane = threadIdx.x & 31;
    int b    = gw >> 5;
    int grp  = gw & 31;
    float* row = out + (size_t)b * OUTW;
    float l = row[512 + grp * 32 + lane];
    float m = l;
#pragma unroll
    for (int o = 16; o > 0; o >>= 1) m = fmaxf(m, __shfl_xor_sync(0xffffffffu, m, o));
    float e = expf(l - m);
    float s = e;
#pragma unroll
    for (int o = 16; o > 0; o >>= 1) s += __shfl_xor_sync(0xffffffffu, s, o);
    float p = (1.f - UNIMIX) * (e / s) + UNIMIX / 32.f;
    float bp = p; int bi = lane;
#pragma unroll
    for (int o = 16; o > 0; o >>= 1) {
        float op = __shfl_xor_sync(0xffffffffu, bp, o);
        int   oi = __shfl_xor_sync(0xffffffffu, bi, o);
        if (op > bp || (op == bp && oi < bi)) { bp = op; bi = oi; }
    }
    row[1536 + grp * 32 + lane] = (lane == bi) ? 1.f : 0.f;
}

// ---------------------------------------------------------------------------
// Launch
// ---------------------------------------------------------------------------
extern "C" void kernel_launch(void* const* d_in, const int* in_sizes, int n_in,
                              void* d_out_, int out_size)
{
    const float* obs   = (const float*)d_in[0];
    const float* act   = (const float*)d_in[1];
    const float* stoch = (const float*)d_in[2];
    const float* deter = (const float*)d_in[3];
    const float* W_in  = (const float*)d_in[4];
    const float* gin   = (const float*)d_in[5];
    const float* bin   = (const float*)d_in[6];
    const float* W_ih  = (const float*)d_in[7];
    const float* W_hh  = (const float*)d_in[8];
    const float* b_ih  = (const float*)d_in[9];
    const float* b_hh  = (const float*)d_in[10];
    const float* W_obs = (const float*)d_in[11];
    const float* gobs  = (const float*)d_in[12];
    const float* bobs  = (const float*)d_in[13];
    const float* W_st  = (const float*)d_in[14];
    const float* b_st  = (const float*)d_in[15];
    float* out = (float*)d_out_;

    float *xbuf, *gi, *gh, *ybuf;
    cudaGetSymbolAddress((void**)&xbuf, g_xbuf);
    cudaGetSymbolAddress((void**)&gi,   g_gi);
    cudaGetSymbolAddress((void**)&gh,   g_gh);
    cudaGetSymbolAddress((void**)&ybuf, g_ybuf);

    cudaFuncSetAttribute(gemm_hmma, cudaFuncAttributeMaxDynamicSharedMemorySize, GEMM_SMEM);
    cudaFuncSetAttribute(gemm_dual, cudaFuncAttributeMaxDynamicSharedMemorySize, GEMM_SMEM);

    const int MT = B / 128;  // 128

    // 1+4) fused: x_pre = [stoch|act] @ W_in^T  AND  gh = deter @ W_hh^T + b_hh
    //      (independent; 2048 CTAs packed into one launch, long CTAs first)
    gemm_dual<<<2048, 512, GEMM_SMEM>>>(stoch, act, W_in, xbuf,
                                        deter, W_hh, b_hh, gh);
    // 2) x = silu(LN(x_pre))
    ln_silu_kernel<<<B, 128>>>(xbuf, xbuf, gin, bin);
    // 3) gi = x @ W_ih^T + b_ih                  (N=1536, K=512)
    gemm_hmma<<<dim3(NGATE / 128, MT), 512, GEMM_SMEM>>>(
        xbuf, HID, HID, nullptr, 0, W_ih, b_ih, gi, NGATE, HID);
    // 5) GRU -> deter_new in d_out[:, 0:512)
    gru_kernel_v4<<<(B * NDETER / 4) / 256, 256>>>(gi, gh, deter, out);
    // 6) y_pre = [deter_new | obs_enc] @ W_obs^T (N=512, K=5632, K1=512)
    gemm_hmma<<<dim3(HID / 128, MT), 512, GEMM_SMEM>>>(
        out, OUTW, NDETER, obs, 5120, W_obs, nullptr, ybuf, HID, KOBS);
    // 7) y = silu(LN(y_pre))
    ln_silu_kernel<<<B, 128>>>(ybuf, ybuf, gobs, bobs);
    // 8) logits = y @ W_stats^T + b_stats -> d_out[:, 512:1536)
    gemm_hmma<<<dim3(NSTATS / 128, MT), 512, GEMM_SMEM>>>(
        ybuf, HID, HID, nullptr, 0, W_st, b_st, out + 512, OUTW, HID);
    // 9) softmax/unimix/argmax one-hot -> d_out[:, 1536:2560)
    softmax_onehot_kernel<<<(B * 32 * 32) / 256, 256>>>(out);
}

// round 15
// speedup vs baseline: 1.3896x; 1.0286x over previous
#include <cuda_runtime.h>
#include <cuda_fp16.h>
#include <math.h>

// ---------------------------------------------------------------------------
// Problem constants
// ---------------------------------------------------------------------------
#define B       16384
#define HID     512
#define NDETER  512
#define NGATE   1536
#define KIN     1084
#define KOBS    5632
#define NSTATS  1024
#define OUTW    2560
#define LNEPS   1e-3f
#define UNIMIX  0.01f
#define LO_SCALE    2048.0f
#define LO_UNSCALE  (1.0f / 2048.0f)

// ---------------------------------------------------------------------------
// Scratch (device globals; no runtime allocation allowed)
// ---------------------------------------------------------------------------
__device__ float g_xbuf[(size_t)B * HID];
__device__ float g_gi  [(size_t)B * NGATE];
__device__ float g_gh  [(size_t)B * NGATE];
__device__ float g_ybuf[(size_t)B * HID];

// ---------------------------------------------------------------------------
// Helpers
// ---------------------------------------------------------------------------
__device__ __forceinline__ unsigned smem_u32(const void* p) {
    unsigned a;
    asm("{ .reg .u64 t; cvta.to.shared.u64 t, %1; cvt.u32.u64 %0, t; }"
        : "=r"(a) : "l"(p));
    return a;
}

#define MMA16816(acc, a, b0v, b1v)                                            \
    asm volatile(                                                             \
        "mma.sync.aligned.m16n8k16.row.col.f32.f16.f16.f32 "                  \
        "{%0,%1,%2,%3}, {%4,%5,%6,%7}, {%8,%9}, {%0,%1,%2,%3};"               \
        : "+f"((acc)[0]), "+f"((acc)[1]), "+f"((acc)[2]), "+f"((acc)[3])      \
        : "r"((a)[0]), "r"((a)[1]), "r"((a)[2]), "r"((a)[3]),                 \
          "r"(b0v), "r"(b1v))

#define LDMX4(r0, r1, r2, r3, addr)                                           \
    asm volatile("ldmatrix.sync.aligned.m8n8.x4.shared.b16 {%0,%1,%2,%3}, [%4];" \
        : "=r"(r0), "=r"(r1), "=r"(r2), "=r"(r3) : "r"(addr))

// ---------------------------------------------------------------------------
// fp16-split (Ootomo, scaled residual) HMMA GEMM body — ROUND-8 BIT-EXACT.
// x = hi + lo/2048 (fp16).  acc0 += hi*hi;  acc1 += hi*lo + lo*hi;
// C = acc0 + acc1/2048 (+bias).  fp32 accumulators everywhere.
// CTA tile 128x128, K-chunk 32, 16 warps (4Mx4N), warp tile 32x32.
// 2-stage smem pipeline: AH@0, AL@10240, BH@20480, BL@30720, pitch 80B,
// stage stride 64KB.
// NUMERICS FROZEN: per-output-element op sequence must not change
// (rel_err must be exactly 9.778108e-4).
// EPI template: 0 = plain store; 1 = logits + per-group-32 argmax one-hot
// (one-hot depends only on argmax of the bit-frozen logits -> safe).
// ---------------------------------------------------------------------------
#define BKF     32
#define PITCH   80
#define AL_REL  10240u
#define BH_REL  20480u
#define STAGE_STRIDE 65536u
#define GEMM_SMEM (2 * 65536)

template<int EPI>
__device__ __forceinline__
void gemm_body(const float* __restrict__ A1, int lda1, int K1,
               const float* __restrict__ A2, int lda2,
               const float* __restrict__ W, const float* __restrict__ bias,
               float* __restrict__ C, int ldc, int K,
               int mBase, int nBase, char* smem)
{
    const unsigned sb = smem_u32(smem);
    const int tid  = threadIdx.x;
    const int lane = tid & 31;
    const int wid  = tid >> 5;              // 0..15
    const int mW   = (wid >> 2) * 32;       // 4 M-groups
    const int nW   = (wid & 3) * 32;        // 4 N-groups

    float acc0[2][4][4];   // hi*hi
    float acc1[2][4][4];   // hi*lo + lo*hi (scaled by 2048)
#pragma unroll
    for (int i = 0; i < 2; i++)
#pragma unroll
        for (int j = 0; j < 4; j++)
#pragma unroll
            for (int c = 0; c < 4; c++) { acc0[i][j][c] = 0.f; acc1[i][j][c] = 0.f; }

    // ---- hoisted global pointers ----
    const int rowq = tid >> 3;             // 0..63
    const int c4b  = (tid & 7) * 4;        // k element offset
    const float* A2b = A2 ? A2 : A1;
    const int    ld2 = A2 ? lda2 : 0;
    const int    c4b2 = A2 ? c4b : 0;
    const float* pA1[2]; const float* pA2[2]; const float* pW[2];
#pragma unroll
    for (int q = 0; q < 2; ++q) {
        const int row = q * 64 + rowq;
        pA1[q] = A1  + (size_t)(mBase + row) * lda1 + c4b;
        pA2[q] = A2b + (size_t)(mBase + row) * ld2  + c4b2;
        pW[q]  = W   + (size_t)(nBase + row) * K    + c4b;
    }

    // ---- hoisted smem bases ----
    const unsigned stsBase0 = sb + (unsigned)(rowq * PITCH + (tid & 7) * 8);
    const unsigned stsBase1 = stsBase0 + STAGE_STRIDE;
    const unsigned aBase0 = sb + (unsigned)((mW + (lane & 15)) * PITCH + (lane >> 4) * 16);
    const unsigned aBase1 = aBase0 + STAGE_STRIDE;
    const unsigned bBase0 = sb + BH_REL
                          + (unsigned)((nW + (lane & 15)) * PITCH + (lane >> 4) * 16);
    const unsigned bBase1 = bBase0 + STAGE_STRIDE;

    const int nch = (K + BKF - 1) / BKF;

    float4 v[4];
    auto ldg_chunk = [&](int k0) {
        const bool seg1 = (k0 < K1);
        const int  kA   = seg1 ? k0 : k0 - K1;
        if (k0 + BKF <= K) {
#pragma unroll
            for (int q = 0; q < 2; ++q) {
                v[q]     = *(const float4*)((seg1 ? pA1[q] : pA2[q]) + kA);
                v[q + 2] = *(const float4*)(pW[q] + k0);
            }
        } else {
            const int rem = K - k0;
#pragma unroll
            for (int q = 0; q < 2; ++q) {
                float4 z = make_float4(0.f, 0.f, 0.f, 0.f);
                v[q]     = (c4b < rem) ? *(const float4*)((seg1 ? pA1[q] : pA2[q]) + kA) : z;
                v[q + 2] = (c4b < rem) ? *(const float4*)(pW[q] + k0) : z;
            }
        }
    };
    auto sts_chunk = [&](unsigned stsB) {
#pragma unroll
        for (int q = 0; q < 4; ++q) {
            const unsigned addr = stsB + (unsigned)((q & 1) * 64 * PITCH)
                                + (q < 2 ? 0u : BH_REL);
            const float4 x = v[q];
            __half2 h01 = __floats2half2_rn(x.x, x.y);
            __half2 h23 = __floats2half2_rn(x.z, x.w);
            float2 f01 = __half22float2(h01);
            float2 f23 = __half22float2(h23);
            __half2 l01 = __floats2half2_rn((x.x - f01.x) * LO_SCALE,
                                            (x.y - f01.y) * LO_SCALE);
            __half2 l23 = __floats2half2_rn((x.z - f23.x) * LO_SCALE,
                                            (x.w - f23.y) * LO_SCALE);
            unsigned uh0 = *(unsigned*)&h01, uh1 = *(unsigned*)&h23;
            unsigned ul0 = *(unsigned*)&l01, ul1 = *(unsigned*)&l23;
            asm volatile("st.shared.v2.b32 [%0], {%1,%2};"
                         :: "r"(addr), "r"(uh0), "r"(uh1) : "memory");
            asm volatile("st.shared.v2.b32 [%0], {%1,%2};"
                         :: "r"(addr + AL_REL), "r"(ul0), "r"(ul1) : "memory");
        }
    };

    ldg_chunk(0);
    sts_chunk(stsBase0);
    __syncthreads();

    for (int it = 0; it < nch; ++it) {
        const unsigned aB = (it & 1) ? aBase1 : aBase0;
        const unsigned bB = (it & 1) ? bBase1 : bBase0;
        if (it + 1 < nch) ldg_chunk((it + 1) * BKF);

#pragma unroll
        for (int kk = 0; kk < 2; ++kk) {
            unsigned bH[4][2], bL[4][2];
#pragma unroll
            for (int np = 0; np < 2; ++np) {
                const unsigned bd = bB + (unsigned)(np * 16 * PITCH + kk * 32);
                unsigned r0, r1, r2, r3;
                LDMX4(r0, r1, r2, r3, bd);
                bH[2 * np][0] = r0; bH[2 * np][1] = r2;
                bH[2 * np + 1][0] = r1; bH[2 * np + 1][1] = r3;
                LDMX4(r0, r1, r2, r3, bd + AL_REL);
                bL[2 * np][0] = r0; bL[2 * np][1] = r2;
                bL[2 * np + 1][0] = r1; bL[2 * np + 1][1] = r3;
            }
#pragma unroll
            for (int mt = 0; mt < 2; ++mt) {
                unsigned aH[4], aL[4];
                const unsigned ad = aB + (unsigned)(mt * 16 * PITCH + kk * 32);
                LDMX4(aH[0], aH[1], aH[2], aH[3], ad);
                LDMX4(aL[0], aL[1], aL[2], aL[3], ad + AL_REL);
#pragma unroll
                for (int nt = 0; nt < 4; ++nt)
                    MMA16816(acc0[mt][nt], aH, bH[nt][0], bH[nt][1]);
#pragma unroll
                for (int nt = 0; nt < 4; ++nt)
                    MMA16816(acc1[mt][nt], aH, bL[nt][0], bL[nt][1]);
#pragma unroll
                for (int nt = 0; nt < 4; ++nt)
                    MMA16816(acc1[mt][nt], aL, bH[nt][0], bH[nt][1]);
            }
        }

        if (it + 1 < nch) sts_chunk((it & 1) ? stsBase0 : stsBase1);
        __syncthreads();
    }

    // ---- epilogue ----
    const int g = lane >> 2, t = lane & 3;
#pragma unroll
    for (int mt = 0; mt < 2; ++mt) {
        float bestV0 = -3.4e38f, bestV1 = -3.4e38f;
        int   bestI0 = 0,        bestI1 = 0;
#pragma unroll
        for (int nt = 0; nt < 4; ++nt) {
            const int row = mBase + mW + mt * 16 + g;
            const int col = nBase + nW + nt * 8 + t * 2;
            float bx = 0.f, by = 0.f;
            if (bias) { bx = bias[col]; by = bias[col + 1]; }
            float2 o0, o1;
            o0.x = fmaf(acc1[mt][nt][0], LO_UNSCALE, acc0[mt][nt][0]) + bx;
            o0.y = fmaf(acc1[mt][nt][1], LO_UNSCALE, acc0[mt][nt][1]) + by;
            o1.x = fmaf(acc1[mt][nt][2], LO_UNSCALE, acc0[mt][nt][2]) + bx;
            o1.y = fmaf(acc1[mt][nt][3], LO_UNSCALE, acc0[mt][nt][3]) + by;
            *(float2*)(C + (size_t)row * ldc + col)       = o0;
            *(float2*)(C + (size_t)(row + 8) * ldc + col) = o1;
            if (EPI == 1) {
                const int gc = nt * 8 + t * 2;   // col within 32-group
                if (o0.x > bestV0) { bestV0 = o0.x; bestI0 = gc; }
                if (o0.y > bestV0) { bestV0 = o0.y; bestI0 = gc + 1; }
                if (o1.x > bestV1) { bestV1 = o1.x; bestI1 = gc; }
                if (o1.y > bestV1) { bestV1 = o1.y; bestI1 = gc + 1; }
            }
        }
        if (EPI == 1) {
            // reduce (max, min-idx) across the 4 lanes sharing row g
#pragma unroll
            for (int off = 1; off <= 2; off <<= 1) {
                float ov0 = __shfl_xor_sync(0xffffffffu, bestV0, off);
                int   oi0 = __shfl_xor_sync(0xffffffffu, bestI0, off);
                if (ov0 > bestV0 || (ov0 == bestV0 && oi0 < bestI0)) { bestV0 = ov0; bestI0 = oi0; }
                float ov1 = __shfl_xor_sync(0xffffffffu, bestV1, off);
                int   oi1 = __shfl_xor_sync(0xffffffffu, bestI1, off);
                if (ov1 > bestV1 || (ov1 == bestV1 && oi1 < bestI1)) { bestV1 = ov1; bestI1 = oi1; }
            }
            // one-hot writes: logits live at C (= out+512); one-hot at +1024
#pragma unroll
            for (int nt = 0; nt < 4; ++nt) {
                const int row = mBase + mW + mt * 16 + g;
                const int col = nBase + nW + nt * 8 + t * 2;
                const int gc  = nt * 8 + t * 2;
                float2 h0, h1;
                h0.x = (gc     == bestI0) ? 1.f : 0.f;
                h0.y = (gc + 1 == bestI0) ? 1.f : 0.f;
                h1.x = (gc     == bestI1) ? 1.f : 0.f;
                h1.y = (gc + 1 == bestI1) ? 1.f : 0.f;
                *(float2*)(C + (size_t)row * ldc + 1024 + col)       = h0;
                *(float2*)(C + (size_t)(row + 8) * ldc + 1024 + col) = h1;
            }
        }
    }
}

// Standard single-GEMM wrapper (2D grid: x = N-tile, y = M-tile)
__global__ __launch_bounds__(512, 1)
void gemm_hmma(const float* __restrict__ A1, int lda1, int K1,
               const float* __restrict__ A2, int lda2,
               const float* __restrict__ W, const float* __restrict__ bias,
               float* __restrict__ C, int ldc, int K)
{
    extern __shared__ char smem[];
    gemm_body<0>(A1, lda1, K1, A2, lda2, W, bias, C, ldc, K,
                 blockIdx.y * 128, blockIdx.x * 128, smem);
}

// G8 + softmax/argmax one-hot fused wrapper. C must be out+512 (ldc=OUTW);
// one-hot goes to C+1024 (= out+1536). One-hot depends only on argmax of
// the bit-frozen logits (unimix softmax is strictly monotone per group).
__global__ __launch_bounds__(512, 1)
void gemm_logits(const float* __restrict__ A1, int lda1, int K1,
                 const float* __restrict__ W, const float* __restrict__ bias,
                 float* __restrict__ C, int ldc, int K)
{
    extern __shared__ char smem[];
    gemm_body<1>(A1, lda1, K1, nullptr, 0, W, bias, C, ldc, K,
                 blockIdx.y * 128, blockIdx.x * 128, smem);
}

// Fused G1 (x_pre) + G4 (gh) wrapper — 1D grid, long G1 CTAs first.
__global__ __launch_bounds__(512, 1)
void gemm_dual(const float* __restrict__ stoch, const float* __restrict__ act,
               const float* __restrict__ W_in, float* __restrict__ xbuf,
               const float* __restrict__ deter, const float* __restrict__ W_hh,
               const float* __restrict__ b_hh, float* __restrict__ gh)
{
    extern __shared__ char smem[];
    const int bid = blockIdx.x;
    if (bid < 512) {
        const int nB = (bid & 3) * 128;
        const int mB = (bid >> 2) * 128;
        gemm_body<0>(stoch, 1024, 1024, act, 60, W_in, nullptr,
                     xbuf, HID, KIN, mB, nB, smem);
    } else {
        const int t  = bid - 512;
        const int nB = (t % 12) * 128;
        const int mB = (t / 12) * 128;
        gemm_body<0>(deter, NDETER, NDETER, nullptr, 0, W_hh, b_hh,
                     gh, NGATE, NDETER, mB, nB, smem);
    }
}

// ---------------------------------------------------------------------------
// LayerNorm(eps=1e-3) + SiLU (rows of 512; 128 threads/row)
// ---------------------------------------------------------------------------
__device__ __forceinline__ float block_reduce_128(float v, float* sm)
{
#pragma unroll
    for (int o = 16; o > 0; o >>= 1) v += __shfl_xor_sync(0xffffffffu, v, o);
    int w = threadIdx.x >> 5;
    if ((threadIdx.x & 31) == 0) sm[w] = v;
    __syncthreads();
    float r = sm[0] + sm[1] + sm[2] + sm[3];
    __syncthreads();
    return r;
}

__global__ void ln_silu_kernel(const float* __restrict__ in, float* __restrict__ out,
                               const float* __restrict__ g, const float* __restrict__ bb)
{
    __shared__ float sm[4];
    const int row = blockIdx.x;
    const float4 v = ((const float4*)(in + (size_t)row * HID))[threadIdx.x];
    float s = v.x + v.y + v.z + v.w;
    float mean = block_reduce_128(s, sm) * (1.f / HID);
    float dx = v.x - mean, dy = v.y - mean, dz = v.z - mean, dw = v.w - mean;
    float q = dx * dx + dy * dy + dz * dz + dw * dw;
    float var = block_reduce_128(q, sm) * (1.f / HID);
    float rs = rsqrtf(var + LNEPS);
    float4 gg = ((const float4*)g)[threadIdx.x];
    float4 bv = ((const float4*)bb)[threadIdx.x];
    float t0 = dx * rs * gg.x + bv.x;
    float t1 = dy * rs * gg.y + bv.y;
    float t2 = dz * rs * gg.z + bv.z;
    float t3 = dw * rs * gg.w + bv.w;
    float4 o;
    o.x = t0 / (1.f + expf(-t0));
    o.y = t1 / (1.f + expf(-t1));
    o.z = t2 / (1.f + expf(-t2));
    o.w = t3 / (1.f + expf(-t3));
    ((float4*)(out + (size_t)row * HID))[threadIdx.x] = o;
}

// ---------------------------------------------------------------------------
// GRU gates (torch order r,z,n) -> deter into d_out cols [0,512)
// float4-vectorized; per-element math identical to scalar -> bit-identical.
// ---------------------------------------------------------------------------
__device__ __forceinline__ float sigmoidf_(float x) { return 1.f / (1.f + expf(-x)); }

__global__ void gru_kernel_v4(const float* __restrict__ gi, const float* __restrict__ gh,
                              const float* __restrict__ deter_old, float* __restrict__ out)
{
    int idx = blockIdx.x * blockDim.x + threadIdx.x;   // over B*512/4
    int b  = idx >> 7;           // 128 quads per row
    int hq = idx & 127;
    size_t base = (size_t)b * NGATE + hq * 4;
    float4 gir = *(const float4*)(gi + base);
    float4 giz = *(const float4*)(gi + base + 512);
    float4 gin = *(const float4*)(gi + base + 1024);
    float4 ghr = *(const float4*)(gh + base);
    float4 ghz = *(const float4*)(gh + base + 512);
    float4 ghn = *(const float4*)(gh + base + 1024);
    float4 dv  = *(const float4*)(deter_old + (size_t)b * NDETER + hq * 4);
    float4 o;
    {
        float r = sigmoidf_(gir.x + ghr.x);
        float z = sigmoidf_(giz.x + ghz.x);
        float n = tanhf(gin.x + r * ghn.x);
        o.x = (1.f - z) * n + z * dv.x;
    }
    {
        float r = sigmoidf_(gir.y + ghr.y);
        float z = sigmoidf_(giz.y + ghz.y);
        float n = tanhf(gin.y + r * ghn.y);
        o.y = (1.f - z) * n + z * dv.y;
    }
    {
        float r = sigmoidf_(gir.z + ghr.z);
        float z = sigmoidf_(giz.z + ghz.z);
        float n = tanhf(gin.z + r * ghn.z);
        o.z = (1.f - z) * n + z * dv.z;
    }
    {
        float r = sigmoidf_(gir.w + ghr.w);
        float z = sigmoidf_(giz.w + ghz.w);
        float n = tanhf(gin.w + r * ghn.w);
        o.w = (1.f - z) * n + z * dv.w;
    }
    *(float4*)(out + (size_t)b * OUTW + hq * 4) = o;
}

// ---------------------------------------------------------------------------
// Launch
// ---------------------------------------------------------------------------
extern "C" void kernel_launch(void* const* d_in, const int* in_sizes, int n_in,
                              void* d_out_, int out_size)
{
    const float* obs   = (const float*)d_in[0];
    const float* act   = (const float*)d_in[1];
    const float* stoch = (const float*)d_in[2];
    const float* deter = (const float*)d_in[3];
    const float* W_in  = (const float*)d_in[4];
    const float* gin   = (const float*)d_in[5];
    const float* bin   = (const float*)d_in[6];
    const float* W_ih  = (const float*)d_in[7];
    const float* W_hh  = (const float*)d_in[8];
    const float* b_ih  = (const float*)d_in[9];
    const float* b_hh  = (const float*)d_in[10];
    const float* W_obs = (const float*)d_in[11];
    const float* gobs  = (const float*)d_in[12];
    const float* bobs  = (const float*)d_in[13];
    const float* W_st  = (const float*)d_in[14];
    const float* b_st  = (const float*)d_in[15];
    float* out = (float*)d_out_;

    float *xbuf, *gi, *gh, *ybuf;
    cudaGetSymbolAddress((void**)&xbuf, g_xbuf);
    cudaGetSymbolAddress((void**)&gi,   g_gi);
    cudaGetSymbolAddress((void**)&gh,   g_gh);
    cudaGetSymbolAddress((void**)&ybuf, g_ybuf);

    cudaFuncSetAttribute(gemm_hmma,   cudaFuncAttributeMaxDynamicSharedMemorySize, GEMM_SMEM);
    cudaFuncSetAttribute(gemm_dual,   cudaFuncAttributeMaxDynamicSharedMemorySize, GEMM_SMEM);
    cudaFuncSetAttribute(gemm_logits, cudaFuncAttributeMaxDynamicSharedMemorySize, GEMM_SMEM);

    const int MT = B / 128;  // 128

    // 1+4) fused: x_pre = [stoch|act] @ W_in^T  AND  gh = deter @ W_hh^T + b_hh
    gemm_dual<<<2048, 512, GEMM_SMEM>>>(stoch, act, W_in, xbuf,
                                        deter, W_hh, b_hh, gh);
    // 2) x = silu(LN(x_pre))
    ln_silu_kernel<<<B, 128>>>(xbuf, xbuf, gin, bin);
    // 3) gi = x @ W_ih^T + b_ih                  (N=1536, K=512)
    gemm_hmma<<<dim3(NGATE / 128, MT), 512, GEMM_SMEM>>>(
        xbuf, HID, HID, nullptr, 0, W_ih, b_ih, gi, NGATE, HID);
    // 5) GRU -> deter_new in d_out[:, 0:512)
    gru_kernel_v4<<<(B * NDETER / 4) / 256, 256>>>(gi, gh, deter, out);
    // 6) y_pre = [deter_new | obs_enc] @ W_obs^T (N=512, K=5632, K1=512)
    gemm_hmma<<<dim3(HID / 128, MT), 512, GEMM_SMEM>>>(
        out, OUTW, NDETER, obs, 5120, W_obs, nullptr, ybuf, HID, KOBS);
    // 7) y = silu(LN(y_pre))
    ln_silu_kernel<<<B, 128>>>(ybuf, ybuf, gobs, bobs);
    // 8+9) logits = y @ W_stats^T + b_stats -> d_out[:, 512:1536)
    //      + fused per-group-32 argmax one-hot -> d_out[:, 1536:2560)
    gemm_logits<<<dim3(NSTATS / 128, MT), 512, GEMM_SMEM>>>(
        ybuf, HID, HID, W_st, b_st, out + 512, OUTW, HID);
}